// round 14
// baseline (speedup 1.0000x reference)
#include <cuda_runtime.h>
#include <cuda_bf16.h>
#include <cstdint>

#define D 128
#define NTOT ((1 << 18) - 1)      // 262143
#define LEAF0 ((1 << 17) - 1)     // 131071
#define LDK 136                    // bf16 pitch -> conflict-free ldmatrix

__device__ float g_raw[NTOT * D];          // embed output (= ret for leaves)
__device__ float g_emb[NTOT * D];          // emb for internal nodes
__device__ float g_contrib[NTOT * D];      // per-child contribution (incl. edge bias)
__device__ int   g_bucket[8 * (NTOT - 1)];
__device__ int   g_count[17 * 8];
__device__ __align__(16) __nv_bfloat16 g_Wt[9 * 2 * D * LDK];  // W^T hi/lo per matrix
__device__ int      g_bar_count;
__device__ unsigned g_bar_gen;

__device__ __forceinline__ uint32_t smem_to_u32(const void* p) {
    uint32_t a;
    asm("{ .reg .u64 t; cvta.to.shared.u64 t, %1; cvt.u32.u64 %0, t; }"
        : "=r"(a) : "l"(p));
    return a;
}
// split x into hi(bf16) + lo(bf16 residual); pack (x,y): low16=x, high16=y
__device__ __forceinline__ void split_pair(float x, float y, uint32_t& h, uint32_t& l) {
    asm("cvt.rn.bf16x2.f32 %0, %1, %2;" : "=r"(h) : "f"(y), "f"(x));
    float hx = __uint_as_float(h << 16);
    float hy = __uint_as_float(h & 0xffff0000u);
    asm("cvt.rn.bf16x2.f32 %0, %1, %2;" : "=r"(l) : "f"(y - hy), "f"(x - hx));
}
__device__ __forceinline__ void mma16816(float c[4], const uint32_t a[4],
                                         uint32_t b0, uint32_t b1) {
    asm volatile(
        "mma.sync.aligned.m16n8k16.row.col.f32.bf16.bf16.f32 "
        "{%0,%1,%2,%3}, {%4,%5,%6,%7}, {%8,%9}, {%0,%1,%2,%3};\n"
        : "+f"(c[0]), "+f"(c[1]), "+f"(c[2]), "+f"(c[3])
        : "r"(a[0]), "r"(a[1]), "r"(a[2]), "r"(a[3]), "r"(b0), "r"(b1));
}
__device__ __forceinline__ void ldsm4(uint32_t& r0, uint32_t& r1,
                                      uint32_t& r2, uint32_t& r3, uint32_t a) {
    asm volatile("ldmatrix.sync.aligned.m8n8.x4.shared.b16 {%0,%1,%2,%3}, [%4];"
                 : "=r"(r0), "=r"(r1), "=r"(r2), "=r"(r3) : "r"(a));
}

// ---- software grid barrier (all blocks co-resident; self-resetting) ----
__device__ __forceinline__ void grid_bar_n(int nbl) {
    __syncthreads();
    if (threadIdx.x == 0) {
        unsigned gen = *((volatile unsigned*)&g_bar_gen);
        __threadfence();
        if (atomicAdd(&g_bar_count, 1) == nbl - 1) {
            g_bar_count = 0;
            __threadfence();
            atomicAdd(&g_bar_gen, 1u);
        } else {
            while (*((volatile unsigned*)&g_bar_gen) == gen) { }
        }
        __threadfence();
    }
    __syncthreads();
}

// ============================================================================
__global__ void bucket_kernel(const int* __restrict__ edges) {
    int c = blockIdx.x * blockDim.x + threadIdx.x + 2047;   // depth >= 11
    if (c >= NTOT) return;
    int d   = 31 - __clz(c + 1);
    int lev = d - 1;                    // parent level 10..16
    int M    = 1 << d;
    int base = 8 * (M - 2);
    int e = edges[c];
    int slot = atomicAdd(&g_count[lev * 8 + e], 1);
    g_bucket[base + e * M + slot] = c;
}

// W^T layout: Wt[n][k] pitch LDK, hi plane then lo plane. Block 0 also zeros
// the bucket counters (this kernel runs BEFORE bucket_kernel).
__global__ void prep_B_kernel(const float* __restrict__ data_W,
                              const float* __restrict__ edge_W) {
    int m = blockIdx.x;                 // 0..7 edges, 8 = data_W
    if (m == 0 && threadIdx.x < 17 * 8) g_count[threadIdx.x] = 0;
    const float* W = (m == 8) ? data_W : (edge_W + (size_t)m * D * D);
    __nv_bfloat16* dst = g_Wt + (size_t)m * 2 * D * LDK;
    for (int idx = threadIdx.x; idx < D * D; idx += blockDim.x) {
        int k = idx >> 7, n = idx & 127;
        float v = W[idx];
        __nv_bfloat16 h = __float2bfloat16(v);
        float hv = __bfloat162float(h);
        __nv_bfloat16 l = __float2bfloat16(v - hv);
        dst[n * LDK + k] = h;
        dst[D * LDK + n * LDK + k] = l;
    }
}

// ---------------------------------------------------------------------------
// Register-pipelined mma.sync GEMM + fused combine. Tile = 128x128, K = 128.
// 512 threads / 16 warps; warp tile m32 x n32; LDG->regs->convert->Ah dbl buf.
// mode 0 = embed (gather data_vecs[data[j]]), 1 = leaf (g_raw), 2 = internal.
// If npar > 0: after a software grid barrier, this launch also computes
//   emb[p] = (raw[p] + contrib[2p+1] + contrib[2p+2]) / 3  for the parents.
// ---------------------------------------------------------------------------
#define SM_WH   0                       // 69632
#define SM_AH0  69632                   // 69632 (hi plane + lo plane @ +128*LDK)
#define SM_AH1  139264                  // 69632
#define SM_BIAS 208896                  // 512
#define SM_IDS  209408                  // 4 * 128 * 4 = 2048
#define SM_TOT  211456

__global__ void __launch_bounds__(512, 1)
mma_gemm_kernel(const int* __restrict__ data,
                const float* __restrict__ data_vecs,
                const float* __restrict__ srcarr,
                const int* __restrict__ counts, int bucket_base, int Mlist,
                const float* __restrict__ bias_all,
                int mode, int nb, int p0, int npar)
{
    extern __shared__ unsigned char smem[];
    __nv_bfloat16* Wh = (__nv_bfloat16*)(smem + SM_WH);
    float* bias_sm = (float*)(smem + SM_BIAS);
    int*   ids_sm  = (int*)(smem + SM_IDS);

    const int tid = threadIdx.x;
    const int e  = (mode == 0) ? 8 : (blockIdx.x / nb);
    const int bi = (mode == 0) ? blockIdx.x : (blockIdx.x % nb);
    const int count = (mode == 0) ? NTOT : counts[e];
    const int ntiles = (count + 127) >> 7;
    const int relu = (mode == 2);

    if (count > 0 && bi < ntiles) {
        const int niter = (ntiles - bi + nb - 1) / nb;

        const uint32_t smem_u = smem_to_u32(smem);
        const int* list = g_bucket + bucket_base + (size_t)e * Mlist;
        float* outbase = (mode == 0) ? g_raw : g_contrib;

        const int fr = tid >> 2;            // fetch row 0..127
        const int fq = tid & 3;             // row quarter (8 float4)

        float4 vreg[8];

        auto ldg_tile = [&](int it) {
            int tile = bi + it * nb;
            int jj = min(tile * 128 + fr, count - 1);
            int id = (mode == 0) ? jj : list[jj];
            if (fq == 0) ids_sm[(it & 3) * 128 + fr] = id;
            const float4* src = (mode == 0)
                ? (const float4*)(data_vecs + (size_t)__ldg(&data[jj]) * D)
                : (const float4*)(srcarr + (size_t)id * D);
            #pragma unroll
            for (int i = 0; i < 8; ++i)
                vreg[i] = src[fq * 8 + i];
        };

        auto convert = [&](int it) {
            __nv_bfloat16* Ah = (__nv_bfloat16*)(smem + ((it & 1) ? SM_AH1 : SM_AH0));
            #pragma unroll
            for (int i = 0; i < 8; ++i) {
                float4 v = vreg[i];
                if (relu) {
                    v.x = fmaxf(v.x, 0.f); v.y = fmaxf(v.y, 0.f);
                    v.z = fmaxf(v.z, 0.f); v.w = fmaxf(v.w, 0.f);
                }
                uint32_t h0, l0, h1, l1;
                split_pair(v.x, v.y, h0, l0);
                split_pair(v.z, v.w, h1, l1);
                int c = fq * 32 + i * 4;
                *(uint2*)(Ah + fr * LDK + c)             = make_uint2(h0, h1);
                *(uint2*)(Ah + 128 * LDK + fr * LDK + c) = make_uint2(l0, l1);
            }
        };

        // ---- prologue ----
        ldg_tile(0);
        {
            const uint4* src = (const uint4*)(g_Wt + (size_t)e * 2 * D * LDK);
            uint4* dst = (uint4*)Wh;
            for (int i = tid; i < 4352; i += 512) dst[i] = src[i];
            const float* bias = (mode == 0) ? bias_all : (bias_all + e * D);
            if (tid < D) bias_sm[tid] = bias[tid];
        }
        convert(0);
        if (niter > 1) ldg_tile(1);
        __syncthreads();

        // ---- warp tiling ----
        const int lane = tid & 31;
        const int warp = tid >> 5;
        const int mq = warp & 3;
        const int nq = warp >> 2;
        const int g  = lane >> 2;
        const int t2 = (lane & 3) * 2;

        uint32_t aAddr[2][2][2], wAddr[2][2];
        #pragma unroll
        for (int b = 0; b < 2; ++b)
            #pragma unroll
            for (int mt = 0; mt < 2; ++mt)
                #pragma unroll
                for (int pl = 0; pl < 2; ++pl)
                    aAddr[b][mt][pl] = smem_u + (b ? SM_AH1 : SM_AH0) +
                        ((pl * 128 + mq * 32 + mt * 16 + (lane & 15)) * LDK
                         + (lane >> 4) * 8) * 2;
        #pragma unroll
        for (int q = 0; q < 2; ++q)
            #pragma unroll
            for (int pl = 0; pl < 2; ++pl)
                wAddr[q][pl] = smem_u + SM_WH +
                    ((pl * 128 + nq * 32 + q * 16 + ((lane >> 4) & 1) * 8 + (lane & 7)) * LDK
                     + ((lane >> 3) & 1) * 8) * 2;

        for (int it = 0; it < niter; ++it) {
            const int pb = it & 1;

            float acc[2][4][4];
            #pragma unroll
            for (int mt = 0; mt < 2; ++mt)
                #pragma unroll
                for (int nt = 0; nt < 4; ++nt)
                    #pragma unroll
                    for (int i = 0; i < 4; ++i) acc[mt][nt][i] = 0.f;

            #pragma unroll
            for (int ks = 0; ks < 8; ++ks) {
                const uint32_t kb = ks * 32;
                uint32_t ah[2][4], al[2][4];
                #pragma unroll
                for (int mt = 0; mt < 2; ++mt) {
                    ldsm4(ah[mt][0], ah[mt][1], ah[mt][2], ah[mt][3],
                          aAddr[pb][mt][0] + kb);
                    ldsm4(al[mt][0], al[mt][1], al[mt][2], al[mt][3],
                          aAddr[pb][mt][1] + kb);
                }
                uint32_t bh[4][2], bl[4][2];
                #pragma unroll
                for (int q = 0; q < 2; ++q) {
                    ldsm4(bh[2 * q][0], bh[2 * q][1], bh[2 * q + 1][0], bh[2 * q + 1][1],
                          wAddr[q][0] + kb);
                    ldsm4(bl[2 * q][0], bl[2 * q][1], bl[2 * q + 1][0], bl[2 * q + 1][1],
                          wAddr[q][1] + kb);
                }
                #pragma unroll
                for (int mt = 0; mt < 2; ++mt)
                    #pragma unroll
                    for (int nt = 0; nt < 4; ++nt) {
                        mma16816(acc[mt][nt], ah[mt], bh[nt][0], bh[nt][1]);   // hi*Whi
                        mma16816(acc[mt][nt], al[mt], bh[nt][0], bh[nt][1]);   // lo*Whi
                        mma16816(acc[mt][nt], ah[mt], bl[nt][0], bl[nt][1]);   // hi*Wlo
                    }
            }

            if (it + 1 < niter) convert(it + 1);
            if (it + 2 < niter) ldg_tile(it + 2);

            {
                const int slot = (it & 3) * 128;
                #pragma unroll
                for (int mt = 0; mt < 2; ++mt) {
                    int rr = mq * 32 + mt * 16 + g;
                    int id0 = ids_sm[slot + rr];
                    int id1 = ids_sm[slot + rr + 8];
                    float* o0 = outbase + (size_t)id0 * D;
                    float* o1 = outbase + (size_t)id1 * D;
                    #pragma unroll
                    for (int nt = 0; nt < 4; ++nt) {
                        int n0 = nq * 32 + nt * 8 + t2;
                        float b0 = bias_sm[n0], b1 = bias_sm[n0 + 1];
                        *(float2*)(o0 + n0) = make_float2(acc[mt][nt][0] + b0,
                                                          acc[mt][nt][1] + b1);
                        *(float2*)(o1 + n0) = make_float2(acc[mt][nt][2] + b0,
                                                          acc[mt][nt][3] + b1);
                    }
                }
            }
            __syncthreads();
        }
    }

    // ---- fused combine for the parent level ----
    if (npar > 0) {
        grid_bar_n(gridDim.x);           // all contribs for this level visible
        const int total = npar * 32;     // float4 elements
        for (int idx = blockIdx.x * 512 + tid; idx < total; idx += gridDim.x * 512) {
            int i = idx >> 5, q = idx & 31;
            int p = p0 + i;
            float4 r  = ((const float4*)(g_raw     + (size_t)p * D))[q];
            float4 c1 = ((const float4*)(g_contrib + (size_t)(2 * p + 1) * D))[q];
            float4 c2 = ((const float4*)(g_contrib + (size_t)(2 * p + 2) * D))[q];
            float4 h = make_float4((r.x + c1.x + c2.x) * (1.f / 3.f),
                                   (r.y + c1.y + c2.y) * (1.f / 3.f),
                                   (r.z + c1.z + c2.z) * (1.f / 3.f),
                                   (r.w + c1.w + c2.w) * (1.f / 3.f));
            ((float4*)(g_emb + (size_t)p * D))[q] = h;
        }
    }
}

// ---------------------------------------------------------------------------
// Fused small levels (l = 9..0) with software grid barrier.
// ---------------------------------------------------------------------------
#define NBL 128
__global__ void small_levels_kernel(const int* __restrict__ edges,
                                    const float* __restrict__ edge_W,
                                    const float* __restrict__ edge_b)
{
    __shared__ float v1[D], v2[D];
    const int tid = threadIdx.x;
    for (int l = 9; l >= 0; --l) {
        const int npar = 1 << l, p0 = npar - 1;
        for (int p = p0 + blockIdx.x; p < p0 + npar; p += NBL) {
            const int c1 = 2 * p + 1, c2 = 2 * p + 2;
            v1[tid] = fmaxf(g_emb[(size_t)c1 * D + tid], 0.f);
            v2[tid] = fmaxf(g_emb[(size_t)c2 * D + tid], 0.f);
            const int e1 = edges[c1], e2 = edges[c2];
            __syncthreads();
            const float* W1 = edge_W + (size_t)e1 * D * D + tid;
            const float* W2 = edge_W + (size_t)e2 * D * D + tid;
            float acc = edge_b[e1 * D + tid] + edge_b[e2 * D + tid];
            #pragma unroll 8
            for (int k = 0; k < D; ++k)
                acc += v1[k] * W1[k * D] + v2[k] * W2[k * D];
            float h = (g_raw[(size_t)p * D + tid] + acc) * (1.f / 3.f);
            g_emb[(size_t)p * D + tid] = h;
            __syncthreads();
        }
        grid_bar_n(NBL);
    }
}

// ---------------------------------------------------------------------------
// Scores: internal -> g_emb, leaves -> g_raw
// ---------------------------------------------------------------------------
__global__ void score_kernel(const float* __restrict__ score_W,
                             float* __restrict__ out)
{
    __shared__ float sW[D];
    const int tid = threadIdx.x;
    if (tid < D) sW[tid] = score_W[tid];
    __syncthreads();
    const int w = tid >> 5, lane = tid & 31;
    const float4 s4 = ((const float4*)sW)[lane];
    const int gw = blockIdx.x * 8 + w;
    const int nw = gridDim.x * 8;
    for (int node = gw; node < NTOT; node += nw) {
        const float* src = (node < LEAF0) ? g_emb : g_raw;
        float4 v = ((const float4*)(src + (size_t)node * D))[lane];
        float d = v.x * s4.x + v.y * s4.y + v.z * s4.z + v.w * s4.w;
        #pragma unroll
        for (int off = 16; off; off >>= 1)
            d += __shfl_xor_sync(0xffffffffu, d, off);
        if (lane == 0) out[node] = d;
    }
}

extern "C" void kernel_launch(void* const* d_in, const int* in_sizes, int n_in,
                              void* d_out, int out_size)
{
    const int*   data      = (const int*)  d_in[0];
    const int*   edges     = (const int*)  d_in[1];
    const float* data_vecs = (const float*)d_in[2];
    const float* data_W    = (const float*)d_in[3];
    const float* data_b    = (const float*)d_in[4];
    const float* edge_W    = (const float*)d_in[5];
    const float* edge_b    = (const float*)d_in[6];
    const float* score_W   = (const float*)d_in[7];
    float* out = (float*)d_out;
    (void)in_sizes; (void)n_in; (void)out_size;

    cudaFuncSetAttribute(mma_gemm_kernel,
                         cudaFuncAttributeMaxDynamicSharedMemorySize, SM_TOT);

    int* d_count;
    cudaGetSymbolAddress((void**)&d_count, g_count);
    float* d_raw;
    cudaGetSymbolAddress((void**)&d_raw, g_raw);
    float* d_emb;
    cudaGetSymbolAddress((void**)&d_emb, g_emb);

    // prep_B also zeros bucket counters -> must precede bucket_kernel
    prep_B_kernel<<<9, 256>>>(data_W, edge_W);
    bucket_kernel<<<(NTOT - 2047 + 255) / 256, 256>>>(edges);

    // Embed (mode 0, no combine)
    mma_gemm_kernel<<<148, 512, SM_TOT>>>(data, data_vecs, nullptr,
                                          nullptr, 0, 0,
                                          data_b, 0, 148, 0, 0);

    // Large levels: l = 16 .. 10 — GEMM over children + fused combine
    for (int l = 16; l >= 10; --l) {
        int dd = l + 1;
        int M2 = 1 << dd;                 // children count at this level
        int base = 8 * (M2 - 2);
        int npar = 1 << l;
        int p0 = npar - 1;
        int tiles_pe = (M2 / 8 + 127) >> 7;
        int nb = tiles_pe; if (nb < 1) nb = 1; if (nb > 18) nb = 18;
        const float* srcarr = (l == 16) ? d_raw : d_emb;
        mma_gemm_kernel<<<8 * nb, 512, SM_TOT>>>(nullptr, nullptr, srcarr,
                                                 d_count + l * 8, base, M2,
                                                 edge_b, (l == 16) ? 1 : 2, nb,
                                                 p0, npar);
    }

    // Small levels fused (l = 9..0)
    small_levels_kernel<<<NBL, 128>>>(edges, edge_W, edge_b);

    score_kernel<<<592, 256>>>(score_W, out);
}

// round 15
// speedup vs baseline: 1.0081x; 1.0081x over previous
#include <cuda_runtime.h>
#include <cuda_bf16.h>
#include <cstdint>

#define D 128
#define NTOT ((1 << 18) - 1)      // 262143
#define LEAF0 ((1 << 17) - 1)     // 131071
#define LDK 136                    // bf16 pitch -> conflict-free ldmatrix

__device__ float g_raw[NTOT * D];          // embed output (= ret for leaves)
__device__ float g_emb[NTOT * D];          // emb for internal nodes
__device__ float g_contrib[NTOT * D];      // per-child contribution (incl. edge bias)
__device__ int   g_bucket[8 * (NTOT - 1)];
__device__ int   g_count[17 * 8];
__device__ __align__(16) __nv_bfloat16 g_Wt[9 * 2 * D * LDK];  // W^T hi/lo per matrix
__device__ int      g_bar_count;
__device__ unsigned g_bar_gen;

__device__ __forceinline__ uint32_t smem_to_u32(const void* p) {
    uint32_t a;
    asm("{ .reg .u64 t; cvta.to.shared.u64 t, %1; cvt.u32.u64 %0, t; }"
        : "=r"(a) : "l"(p));
    return a;
}
// split x into hi(bf16) + lo(bf16 residual); pack (x,y): low16=x, high16=y
__device__ __forceinline__ void split_pair(float x, float y, uint32_t& h, uint32_t& l) {
    asm("cvt.rn.bf16x2.f32 %0, %1, %2;" : "=r"(h) : "f"(y), "f"(x));
    float hx = __uint_as_float(h << 16);
    float hy = __uint_as_float(h & 0xffff0000u);
    asm("cvt.rn.bf16x2.f32 %0, %1, %2;" : "=r"(l) : "f"(y - hy), "f"(x - hx));
}
__device__ __forceinline__ void mma16816(float c[4], const uint32_t a[4],
                                         uint32_t b0, uint32_t b1) {
    asm volatile(
        "mma.sync.aligned.m16n8k16.row.col.f32.bf16.bf16.f32 "
        "{%0,%1,%2,%3}, {%4,%5,%6,%7}, {%8,%9}, {%0,%1,%2,%3};\n"
        : "+f"(c[0]), "+f"(c[1]), "+f"(c[2]), "+f"(c[3])
        : "r"(a[0]), "r"(a[1]), "r"(a[2]), "r"(a[3]), "r"(b0), "r"(b1));
}
__device__ __forceinline__ void ldsm4(uint32_t& r0, uint32_t& r1,
                                      uint32_t& r2, uint32_t& r3, uint32_t a) {
    asm volatile("ldmatrix.sync.aligned.m8n8.x4.shared.b16 {%0,%1,%2,%3}, [%4];"
                 : "=r"(r0), "=r"(r1), "=r"(r2), "=r"(r3) : "r"(a));
}

// ---- software grid barrier (all blocks co-resident; self-resetting) ----
__device__ __forceinline__ void grid_bar_n(int nbl) {
    __syncthreads();
    if (threadIdx.x == 0) {
        unsigned gen = *((volatile unsigned*)&g_bar_gen);
        __threadfence();
        if (atomicAdd(&g_bar_count, 1) == nbl - 1) {
            g_bar_count = 0;
            __threadfence();
            atomicAdd(&g_bar_gen, 1u);
        } else {
            while (*((volatile unsigned*)&g_bar_gen) == gen) { }
        }
        __threadfence();
    }
    __syncthreads();
}

// ============================================================================
__global__ void bucket_kernel(const int* __restrict__ edges) {
    int c = blockIdx.x * blockDim.x + threadIdx.x + 2047;   // depth >= 11
    if (c >= NTOT) return;
    int d   = 31 - __clz(c + 1);
    int lev = d - 1;                    // parent level 10..16
    int M    = 1 << d;
    int base = 8 * (M - 2);
    int e = edges[c];
    int slot = atomicAdd(&g_count[lev * 8 + e], 1);
    g_bucket[base + e * M + slot] = c;
}

// W^T layout: Wt[n][k] pitch LDK, hi plane then lo plane. Block 0 also zeros
// the bucket counters (this kernel runs BEFORE bucket_kernel).
__global__ void prep_B_kernel(const float* __restrict__ data_W,
                              const float* __restrict__ edge_W) {
    int m = blockIdx.x;                 // 0..7 edges, 8 = data_W
    if (m == 0 && threadIdx.x < 17 * 8) g_count[threadIdx.x] = 0;
    const float* W = (m == 8) ? data_W : (edge_W + (size_t)m * D * D);
    __nv_bfloat16* dst = g_Wt + (size_t)m * 2 * D * LDK;
    for (int idx = threadIdx.x; idx < D * D; idx += blockDim.x) {
        int k = idx >> 7, n = idx & 127;
        float v = W[idx];
        __nv_bfloat16 h = __float2bfloat16(v);
        float hv = __bfloat162float(h);
        __nv_bfloat16 l = __float2bfloat16(v - hv);
        dst[n * LDK + k] = h;
        dst[D * LDK + n * LDK + k] = l;
    }
}

// ---------------------------------------------------------------------------
// Register-pipelined mma.sync GEMM + fused combine. Tile = 128x128, K = 128.
// 512 threads / 16 warps; warp tile m32 x n32; LDG->regs->convert->Ah dbl buf.
// mode 0 = embed (gather data_vecs[data[j]]), 1 = leaf (g_raw), 2 = internal.
// If npar > 0: after a software grid barrier, this launch also computes
//   emb[p] = (raw[p] + contrib[2p+1] + contrib[2p+2]) / 3  for the parents.
// ---------------------------------------------------------------------------
#define SM_WH   0                       // 69632
#define SM_AH0  69632                   // 69632 (hi plane + lo plane @ +128*LDK)
#define SM_AH1  139264                  // 69632
#define SM_BIAS 208896                  // 512
#define SM_IDS  209408                  // 4 * 128 * 4 = 2048
#define SM_TOT  211456

__global__ void __launch_bounds__(512, 1)
mma_gemm_kernel(const int* __restrict__ data,
                const float* __restrict__ data_vecs,
                const float* __restrict__ srcarr,
                const int* __restrict__ counts, int bucket_base, int Mlist,
                const float* __restrict__ bias_all,
                int mode, int nb, int p0, int npar)
{
    extern __shared__ unsigned char smem[];
    __nv_bfloat16* Wh = (__nv_bfloat16*)(smem + SM_WH);
    float* bias_sm = (float*)(smem + SM_BIAS);
    int*   ids_sm  = (int*)(smem + SM_IDS);

    const int tid = threadIdx.x;
    const int e  = (mode == 0) ? 8 : (blockIdx.x / nb);
    const int bi = (mode == 0) ? blockIdx.x : (blockIdx.x % nb);
    const int count = (mode == 0) ? NTOT : counts[e];
    const int ntiles = (count + 127) >> 7;
    const int relu = (mode == 2);

    if (count > 0 && bi < ntiles) {
        const int niter = (ntiles - bi + nb - 1) / nb;

        const uint32_t smem_u = smem_to_u32(smem);
        const int* list = g_bucket + bucket_base + (size_t)e * Mlist;
        float* outbase = (mode == 0) ? g_raw : g_contrib;

        const int fr = tid >> 2;            // fetch row 0..127
        const int fq = tid & 3;             // row quarter (8 float4)

        float4 vreg[8];

        auto ldg_tile = [&](int it) {
            int tile = bi + it * nb;
            int jj = min(tile * 128 + fr, count - 1);
            int id = (mode == 0) ? jj : list[jj];
            if (fq == 0) ids_sm[(it & 3) * 128 + fr] = id;
            const float4* src = (mode == 0)
                ? (const float4*)(data_vecs + (size_t)__ldg(&data[jj]) * D)
                : (const float4*)(srcarr + (size_t)id * D);
            #pragma unroll
            for (int i = 0; i < 8; ++i)
                vreg[i] = src[fq * 8 + i];
        };

        auto convert = [&](int it) {
            __nv_bfloat16* Ah = (__nv_bfloat16*)(smem + ((it & 1) ? SM_AH1 : SM_AH0));
            #pragma unroll
            for (int i = 0; i < 8; ++i) {
                float4 v = vreg[i];
                if (relu) {
                    v.x = fmaxf(v.x, 0.f); v.y = fmaxf(v.y, 0.f);
                    v.z = fmaxf(v.z, 0.f); v.w = fmaxf(v.w, 0.f);
                }
                uint32_t h0, l0, h1, l1;
                split_pair(v.x, v.y, h0, l0);
                split_pair(v.z, v.w, h1, l1);
                int c = fq * 32 + i * 4;
                *(uint2*)(Ah + fr * LDK + c)             = make_uint2(h0, h1);
                *(uint2*)(Ah + 128 * LDK + fr * LDK + c) = make_uint2(l0, l1);
            }
        };

        // ---- prologue ----
        ldg_tile(0);
        {
            const uint4* src = (const uint4*)(g_Wt + (size_t)e * 2 * D * LDK);
            uint4* dst = (uint4*)Wh;
            for (int i = tid; i < 4352; i += 512) dst[i] = src[i];
            const float* bias = (mode == 0) ? bias_all : (bias_all + e * D);
            if (tid < D) bias_sm[tid] = bias[tid];
        }
        convert(0);
        if (niter > 1) ldg_tile(1);
        __syncthreads();

        // ---- warp tiling ----
        const int lane = tid & 31;
        const int warp = tid >> 5;
        const int mq = warp & 3;
        const int nq = warp >> 2;
        const int g  = lane >> 2;
        const int t2 = (lane & 3) * 2;

        uint32_t aAddr[2][2][2], wAddr[2][2];
        #pragma unroll
        for (int b = 0; b < 2; ++b)
            #pragma unroll
            for (int mt = 0; mt < 2; ++mt)
                #pragma unroll
                for (int pl = 0; pl < 2; ++pl)
                    aAddr[b][mt][pl] = smem_u + (b ? SM_AH1 : SM_AH0) +
                        ((pl * 128 + mq * 32 + mt * 16 + (lane & 15)) * LDK
                         + (lane >> 4) * 8) * 2;
        #pragma unroll
        for (int q = 0; q < 2; ++q)
            #pragma unroll
            for (int pl = 0; pl < 2; ++pl)
                wAddr[q][pl] = smem_u + SM_WH +
                    ((pl * 128 + nq * 32 + q * 16 + ((lane >> 4) & 1) * 8 + (lane & 7)) * LDK
                     + ((lane >> 3) & 1) * 8) * 2;

        for (int it = 0; it < niter; ++it) {
            const int pb = it & 1;

            float acc[2][4][4];
            #pragma unroll
            for (int mt = 0; mt < 2; ++mt)
                #pragma unroll
                for (int nt = 0; nt < 4; ++nt)
                    #pragma unroll
                    for (int i = 0; i < 4; ++i) acc[mt][nt][i] = 0.f;

            #pragma unroll
            for (int ks = 0; ks < 8; ++ks) {
                const uint32_t kb = ks * 32;
                uint32_t ah[2][4], al[2][4];
                #pragma unroll
                for (int mt = 0; mt < 2; ++mt) {
                    ldsm4(ah[mt][0], ah[mt][1], ah[mt][2], ah[mt][3],
                          aAddr[pb][mt][0] + kb);
                    ldsm4(al[mt][0], al[mt][1], al[mt][2], al[mt][3],
                          aAddr[pb][mt][1] + kb);
                }
                uint32_t bh[4][2], bl[4][2];
                #pragma unroll
                for (int q = 0; q < 2; ++q) {
                    ldsm4(bh[2 * q][0], bh[2 * q][1], bh[2 * q + 1][0], bh[2 * q + 1][1],
                          wAddr[q][0] + kb);
                    ldsm4(bl[2 * q][0], bl[2 * q][1], bl[2 * q + 1][0], bl[2 * q + 1][1],
                          wAddr[q][1] + kb);
                }
                #pragma unroll
                for (int mt = 0; mt < 2; ++mt)
                    #pragma unroll
                    for (int nt = 0; nt < 4; ++nt) {
                        mma16816(acc[mt][nt], ah[mt], bh[nt][0], bh[nt][1]);   // hi*Whi
                        mma16816(acc[mt][nt], al[mt], bh[nt][0], bh[nt][1]);   // lo*Whi
                        mma16816(acc[mt][nt], ah[mt], bl[nt][0], bl[nt][1]);   // hi*Wlo
                    }
            }

            if (it + 1 < niter) convert(it + 1);
            if (it + 2 < niter) ldg_tile(it + 2);

            {
                const int slot = (it & 3) * 128;
                #pragma unroll
                for (int mt = 0; mt < 2; ++mt) {
                    int rr = mq * 32 + mt * 16 + g;
                    int id0 = ids_sm[slot + rr];
                    int id1 = ids_sm[slot + rr + 8];
                    float* o0 = outbase + (size_t)id0 * D;
                    float* o1 = outbase + (size_t)id1 * D;
                    #pragma unroll
                    for (int nt = 0; nt < 4; ++nt) {
                        int n0 = nq * 32 + nt * 8 + t2;
                        float b0 = bias_sm[n0], b1 = bias_sm[n0 + 1];
                        *(float2*)(o0 + n0) = make_float2(acc[mt][nt][0] + b0,
                                                          acc[mt][nt][1] + b1);
                        *(float2*)(o1 + n0) = make_float2(acc[mt][nt][2] + b0,
                                                          acc[mt][nt][3] + b1);
                    }
                }
            }
            __syncthreads();
        }
    }

    // ---- fused combine for the parent level ----
    if (npar > 0) {
        grid_bar_n(gridDim.x);           // all contribs for this level visible
        const int total = npar * 32;     // float4 elements
        for (int idx = blockIdx.x * 512 + tid; idx < total; idx += gridDim.x * 512) {
            int i = idx >> 5, q = idx & 31;
            int p = p0 + i;
            float4 r  = ((const float4*)(g_raw     + (size_t)p * D))[q];
            float4 c1 = ((const float4*)(g_contrib + (size_t)(2 * p + 1) * D))[q];
            float4 c2 = ((const float4*)(g_contrib + (size_t)(2 * p + 2) * D))[q];
            float4 h = make_float4((r.x + c1.x + c2.x) * (1.f / 3.f),
                                   (r.y + c1.y + c2.y) * (1.f / 3.f),
                                   (r.z + c1.z + c2.z) * (1.f / 3.f),
                                   (r.w + c1.w + c2.w) * (1.f / 3.f));
            ((float4*)(g_emb + (size_t)p * D))[q] = h;
        }
    }
}

// ---------------------------------------------------------------------------
// Fused small levels (l = 9..0) with software grid barrier.
// ---------------------------------------------------------------------------
#define NBL 128
__global__ void small_levels_kernel(const int* __restrict__ edges,
                                    const float* __restrict__ edge_W,
                                    const float* __restrict__ edge_b)
{
    __shared__ float v1[D], v2[D];
    const int tid = threadIdx.x;
    for (int l = 9; l >= 0; --l) {
        const int npar = 1 << l, p0 = npar - 1;
        for (int p = p0 + blockIdx.x; p < p0 + npar; p += NBL) {
            const int c1 = 2 * p + 1, c2 = 2 * p + 2;
            v1[tid] = fmaxf(g_emb[(size_t)c1 * D + tid], 0.f);
            v2[tid] = fmaxf(g_emb[(size_t)c2 * D + tid], 0.f);
            const int e1 = edges[c1], e2 = edges[c2];
            __syncthreads();
            const float* W1 = edge_W + (size_t)e1 * D * D + tid;
            const float* W2 = edge_W + (size_t)e2 * D * D + tid;
            float acc = edge_b[e1 * D + tid] + edge_b[e2 * D + tid];
            #pragma unroll 8
            for (int k = 0; k < D; ++k)
                acc += v1[k] * W1[k * D] + v2[k] * W2[k * D];
            float h = (g_raw[(size_t)p * D + tid] + acc) * (1.f / 3.f);
            g_emb[(size_t)p * D + tid] = h;
            __syncthreads();
        }
        grid_bar_n(NBL);
    }
}

// ---------------------------------------------------------------------------
// Scores: internal -> g_emb, leaves -> g_raw
// ---------------------------------------------------------------------------
__global__ void score_kernel(const float* __restrict__ score_W,
                             float* __restrict__ out)
{
    __shared__ float sW[D];
    const int tid = threadIdx.x;
    if (tid < D) sW[tid] = score_W[tid];
    __syncthreads();
    const int w = tid >> 5, lane = tid & 31;
    const float4 s4 = ((const float4*)sW)[lane];
    const int gw = blockIdx.x * 8 + w;
    const int nw = gridDim.x * 8;
    for (int node = gw; node < NTOT; node += nw) {
        const float* src = (node < LEAF0) ? g_emb : g_raw;
        float4 v = ((const float4*)(src + (size_t)node * D))[lane];
        float d = v.x * s4.x + v.y * s4.y + v.z * s4.z + v.w * s4.w;
        #pragma unroll
        for (int off = 16; off; off >>= 1)
            d += __shfl_xor_sync(0xffffffffu, d, off);
        if (lane == 0) out[node] = d;
    }
}

extern "C" void kernel_launch(void* const* d_in, const int* in_sizes, int n_in,
                              void* d_out, int out_size)
{
    const int*   data      = (const int*)  d_in[0];
    const int*   edges     = (const int*)  d_in[1];
    const float* data_vecs = (const float*)d_in[2];
    const float* data_W    = (const float*)d_in[3];
    const float* data_b    = (const float*)d_in[4];
    const float* edge_W    = (const float*)d_in[5];
    const float* edge_b    = (const float*)d_in[6];
    const float* score_W   = (const float*)d_in[7];
    float* out = (float*)d_out;
    (void)in_sizes; (void)n_in; (void)out_size;

    cudaFuncSetAttribute(mma_gemm_kernel,
                         cudaFuncAttributeMaxDynamicSharedMemorySize, SM_TOT);

    int* d_count;
    cudaGetSymbolAddress((void**)&d_count, g_count);
    float* d_raw;
    cudaGetSymbolAddress((void**)&d_raw, g_raw);
    float* d_emb;
    cudaGetSymbolAddress((void**)&d_emb, g_emb);

    // prep_B also zeros bucket counters -> must precede bucket_kernel
    prep_B_kernel<<<9, 256>>>(data_W, edge_W);
    bucket_kernel<<<(NTOT - 2047 + 255) / 256, 256>>>(edges);

    // Embed (mode 0, no combine)
    mma_gemm_kernel<<<148, 512, SM_TOT>>>(data, data_vecs, nullptr,
                                          nullptr, 0, 0,
                                          data_b, 0, 148, 0, 0);

    // Large levels: l = 16 .. 10 — GEMM over children + fused combine
    for (int l = 16; l >= 10; --l) {
        int dd = l + 1;
        int M2 = 1 << dd;                 // children count at this level
        int base = 8 * (M2 - 2);
        int npar = 1 << l;
        int p0 = npar - 1;
        int tiles_pe = (M2 / 8 + 127) >> 7;
        int nb = tiles_pe; if (nb < 1) nb = 1; if (nb > 18) nb = 18;
        const float* srcarr = (l == 16) ? d_raw : d_emb;
        mma_gemm_kernel<<<8 * nb, 512, SM_TOT>>>(nullptr, nullptr, srcarr,
                                                 d_count + l * 8, base, M2,
                                                 edge_b, (l == 16) ? 1 : 2, nb,
                                                 p0, npar);
    }

    // Small levels fused (l = 9..0)
    small_levels_kernel<<<NBL, 128>>>(edges, edge_W, edge_b);

    score_kernel<<<592, 256>>>(score_W, out);
}

// round 16
// speedup vs baseline: 1.0196x; 1.0114x over previous
#include <cuda_runtime.h>
#include <cuda_bf16.h>
#include <cstdint>

#define D 128
#define NTOT ((1 << 18) - 1)      // 262143
#define LEAF0 ((1 << 17) - 1)     // 131071
#define LDK 136                    // bf16 pitch -> conflict-free ldmatrix

__device__ float g_raw[NTOT * D];          // embed output (= ret for leaves)
__device__ float g_emb[NTOT * D];          // emb for internal nodes
__device__ float g_contrib[NTOT * D];      // per-child contribution (incl. edge bias)
__device__ int   g_bucket[8 * (NTOT - 1)];
__device__ int   g_count[17 * 8];
__device__ __align__(16) __nv_bfloat16 g_Wt[9 * 2 * D * LDK];  // W^T hi/lo per matrix
__device__ int      g_bar_count;
__device__ unsigned g_bar_gen;

__device__ __forceinline__ uint32_t smem_to_u32(const void* p) {
    uint32_t a;
    asm("{ .reg .u64 t; cvta.to.shared.u64 t, %1; cvt.u32.u64 %0, t; }"
        : "=r"(a) : "l"(p));
    return a;
}
// split x into hi(bf16) + lo(bf16 residual); pack (x,y): low16=x, high16=y
__device__ __forceinline__ void split_pair(float x, float y, uint32_t& h, uint32_t& l) {
    asm("cvt.rn.bf16x2.f32 %0, %1, %2;" : "=r"(h) : "f"(y), "f"(x));
    float hx = __uint_as_float(h << 16);
    float hy = __uint_as_float(h & 0xffff0000u);
    asm("cvt.rn.bf16x2.f32 %0, %1, %2;" : "=r"(l) : "f"(y - hy), "f"(x - hx));
}
__device__ __forceinline__ void mma16816(float c[4], const uint32_t a[4],
                                         uint32_t b0, uint32_t b1) {
    asm volatile(
        "mma.sync.aligned.m16n8k16.row.col.f32.bf16.bf16.f32 "
        "{%0,%1,%2,%3}, {%4,%5,%6,%7}, {%8,%9}, {%0,%1,%2,%3};\n"
        : "+f"(c[0]), "+f"(c[1]), "+f"(c[2]), "+f"(c[3])
        : "r"(a[0]), "r"(a[1]), "r"(a[2]), "r"(a[3]), "r"(b0), "r"(b1));
}
__device__ __forceinline__ void ldsm4(uint32_t& r0, uint32_t& r1,
                                      uint32_t& r2, uint32_t& r3, uint32_t a) {
    asm volatile("ldmatrix.sync.aligned.m8n8.x4.shared.b16 {%0,%1,%2,%3}, [%4];"
                 : "=r"(r0), "=r"(r1), "=r"(r2), "=r"(r3) : "r"(a));
}

// ---- software grid barrier (co-resident blocks; self-resetting) ----
__device__ __forceinline__ void grid_bar_n(int nbl) {
    __syncthreads();
    if (threadIdx.x == 0) {
        unsigned gen = *((volatile unsigned*)&g_bar_gen);
        __threadfence();
        if (atomicAdd(&g_bar_count, 1) == nbl - 1) {
            g_bar_count = 0;
            __threadfence();
            atomicAdd(&g_bar_gen, 1u);
        } else {
            while (*((volatile unsigned*)&g_bar_gen) == gen) { }
        }
        __threadfence();
    }
    __syncthreads();
}

// ============================================================================
__global__ void bucket_kernel(const int* __restrict__ edges) {
    int c = blockIdx.x * blockDim.x + threadIdx.x + 2047;   // depth >= 11
    if (c >= NTOT) return;
    int d   = 31 - __clz(c + 1);
    int lev = d - 1;                    // parent level 10..16
    int M    = 1 << d;
    int base = 8 * (M - 2);
    int e = edges[c];
    int slot = atomicAdd(&g_count[lev * 8 + e], 1);
    g_bucket[base + e * M + slot] = c;
}

// W^T layout: Wt[n][k] pitch LDK, hi plane then lo plane. Block 0 also zeros
// the bucket counters (runs BEFORE bucket_kernel).
__global__ void prep_B_kernel(const float* __restrict__ data_W,
                              const float* __restrict__ edge_W) {
    int m = blockIdx.x;                 // 0..7 edges, 8 = data_W
    if (m == 0 && threadIdx.x < 17 * 8) g_count[threadIdx.x] = 0;
    const float* W = (m == 8) ? data_W : (edge_W + (size_t)m * D * D);
    __nv_bfloat16* dst = g_Wt + (size_t)m * 2 * D * LDK;
    for (int idx = threadIdx.x; idx < D * D; idx += blockDim.x) {
        int k = idx >> 7, n = idx & 127;
        float v = W[idx];
        __nv_bfloat16 h = __float2bfloat16(v);
        float hv = __bfloat162float(h);
        __nv_bfloat16 l = __float2bfloat16(v - hv);
        dst[n * LDK + k] = h;
        dst[D * LDK + n * LDK + k] = l;
    }
}

// ---------------------------------------------------------------------------
// Register-pipelined mma.sync GEMM (R12 engine). Tile = 128x128, K = 128.
// mode 0 = embed: also computes LEAF scores in the epilogue (out[node] for
//          node >= LEAF0), reducing partials through padded smem.
// mode 1 = leaf children (g_raw), mode 2 = internal children (g_emb + relu).
// ---------------------------------------------------------------------------
#define SM_WH   0                       // 69632
#define SM_AH0  69632                   // 69632 (hi plane + lo plane @ +128*LDK)
#define SM_AH1  139264                  // 69632
#define SM_BIAS 208896                  // 512
#define SM_IDS  209408                  // 4 * 128 * 4 = 2048
#define SM_SC   211456                  // 128 * 17 * 4 = 8704 (score partials)
#define SM_SW   220160                  // 512 (score_W)
#define SM_TOT  220672

__global__ void __launch_bounds__(512, 1)
mma_gemm_kernel(const int* __restrict__ data,
                const float* __restrict__ data_vecs,
                const float* __restrict__ srcarr,
                const int* __restrict__ counts, int bucket_base, int Mlist,
                const float* __restrict__ bias_all,
                int mode, int nb,
                const float* __restrict__ score_W, float* __restrict__ out)
{
    extern __shared__ unsigned char smem[];
    __nv_bfloat16* Wh = (__nv_bfloat16*)(smem + SM_WH);
    float* bias_sm = (float*)(smem + SM_BIAS);
    int*   ids_sm  = (int*)(smem + SM_IDS);
    float* sc_sm   = (float*)(smem + SM_SC);
    float* sw_sm   = (float*)(smem + SM_SW);

    const int tid = threadIdx.x;
    const int e  = (mode == 0) ? 8 : (blockIdx.x / nb);
    const int bi = (mode == 0) ? blockIdx.x : (blockIdx.x % nb);
    const int count = (mode == 0) ? NTOT : counts[e];
    if (count == 0) return;
    const int ntiles = (count + 127) >> 7;
    if (bi >= ntiles) return;
    const int niter = (ntiles - bi + nb - 1) / nb;
    const int relu = (mode == 2);

    const uint32_t smem_u = smem_to_u32(smem);
    const int* list = g_bucket + bucket_base + (size_t)e * Mlist;
    float* outbase = (mode == 0) ? g_raw : g_contrib;

    const int fr = tid >> 2;            // fetch row 0..127
    const int fq = tid & 3;             // row quarter (8 float4)

    float4 vreg[8];

    auto ldg_tile = [&](int it) {
        int tile = bi + it * nb;
        int jj = min(tile * 128 + fr, count - 1);
        int id = (mode == 0) ? jj : list[jj];
        if (fq == 0) ids_sm[(it & 3) * 128 + fr] = id;
        const float4* src = (mode == 0)
            ? (const float4*)(data_vecs + (size_t)__ldg(&data[jj]) * D)
            : (const float4*)(srcarr + (size_t)id * D);
        #pragma unroll
        for (int i = 0; i < 8; ++i)
            vreg[i] = src[fq * 8 + i];
    };

    auto convert = [&](int it) {
        __nv_bfloat16* Ah = (__nv_bfloat16*)(smem + ((it & 1) ? SM_AH1 : SM_AH0));
        #pragma unroll
        for (int i = 0; i < 8; ++i) {
            float4 v = vreg[i];
            if (relu) {
                v.x = fmaxf(v.x, 0.f); v.y = fmaxf(v.y, 0.f);
                v.z = fmaxf(v.z, 0.f); v.w = fmaxf(v.w, 0.f);
            }
            uint32_t h0, l0, h1, l1;
            split_pair(v.x, v.y, h0, l0);
            split_pair(v.z, v.w, h1, l1);
            int c = fq * 32 + i * 4;
            *(uint2*)(Ah + fr * LDK + c)             = make_uint2(h0, h1);
            *(uint2*)(Ah + 128 * LDK + fr * LDK + c) = make_uint2(l0, l1);
        }
    };

    // ---- prologue ----
    ldg_tile(0);
    {
        const uint4* src = (const uint4*)(g_Wt + (size_t)e * 2 * D * LDK);
        uint4* dst = (uint4*)Wh;
        for (int i = tid; i < 4352; i += 512) dst[i] = src[i];
        const float* bias = (mode == 0) ? bias_all : (bias_all + e * D);
        if (tid < D) bias_sm[tid] = bias[tid];
        if (mode == 0 && tid >= 128 && tid < 256) sw_sm[tid - 128] = score_W[tid - 128];
    }
    convert(0);
    if (niter > 1) ldg_tile(1);
    __syncthreads();

    // ---- warp tiling ----
    const int lane = tid & 31;
    const int warp = tid >> 5;
    const int mq = warp & 3;
    const int nq = warp >> 2;
    const int g  = lane >> 2;
    const int t2 = (lane & 3) * 2;
    const int slot4 = nq * 4 + (lane & 3);   // score partial slot 0..15

    uint32_t aAddr[2][2][2], wAddr[2][2];
    #pragma unroll
    for (int b = 0; b < 2; ++b)
        #pragma unroll
        for (int mt = 0; mt < 2; ++mt)
            #pragma unroll
            for (int pl = 0; pl < 2; ++pl)
                aAddr[b][mt][pl] = smem_u + (b ? SM_AH1 : SM_AH0) +
                    ((pl * 128 + mq * 32 + mt * 16 + (lane & 15)) * LDK
                     + (lane >> 4) * 8) * 2;
    #pragma unroll
    for (int q = 0; q < 2; ++q)
        #pragma unroll
        for (int pl = 0; pl < 2; ++pl)
            wAddr[q][pl] = smem_u + SM_WH +
                ((pl * 128 + nq * 32 + q * 16 + ((lane >> 4) & 1) * 8 + (lane & 7)) * LDK
                 + ((lane >> 3) & 1) * 8) * 2;

    for (int it = 0; it < niter; ++it) {
        const int pb = it & 1;

        float acc[2][4][4];
        #pragma unroll
        for (int mt = 0; mt < 2; ++mt)
            #pragma unroll
            for (int nt = 0; nt < 4; ++nt)
                #pragma unroll
                for (int i = 0; i < 4; ++i) acc[mt][nt][i] = 0.f;

        #pragma unroll
        for (int ks = 0; ks < 8; ++ks) {
            const uint32_t kb = ks * 32;
            uint32_t ah[2][4], al[2][4];
            #pragma unroll
            for (int mt = 0; mt < 2; ++mt) {
                ldsm4(ah[mt][0], ah[mt][1], ah[mt][2], ah[mt][3],
                      aAddr[pb][mt][0] + kb);
                ldsm4(al[mt][0], al[mt][1], al[mt][2], al[mt][3],
                      aAddr[pb][mt][1] + kb);
            }
            uint32_t bh[4][2], bl[4][2];
            #pragma unroll
            for (int q = 0; q < 2; ++q) {
                ldsm4(bh[2 * q][0], bh[2 * q][1], bh[2 * q + 1][0], bh[2 * q + 1][1],
                      wAddr[q][0] + kb);
                ldsm4(bl[2 * q][0], bl[2 * q][1], bl[2 * q + 1][0], bl[2 * q + 1][1],
                      wAddr[q][1] + kb);
            }
            #pragma unroll
            for (int mt = 0; mt < 2; ++mt)
                #pragma unroll
                for (int nt = 0; nt < 4; ++nt) {
                    mma16816(acc[mt][nt], ah[mt], bh[nt][0], bh[nt][1]);   // hi*Whi
                    mma16816(acc[mt][nt], al[mt], bh[nt][0], bh[nt][1]);   // lo*Whi
                    mma16816(acc[mt][nt], ah[mt], bl[nt][0], bl[nt][1]);   // hi*Wlo
                }
        }

        if (it + 1 < niter) convert(it + 1);
        if (it + 2 < niter) ldg_tile(it + 2);

        // ---- epilogue (+ leaf-score partials for mode 0) ----
        {
            const int slot = (it & 3) * 128;
            #pragma unroll
            for (int mt = 0; mt < 2; ++mt) {
                int rr = mq * 32 + mt * 16 + g;
                int id0 = ids_sm[slot + rr];
                int id1 = ids_sm[slot + rr + 8];
                float* o0 = outbase + (size_t)id0 * D;
                float* o1 = outbase + (size_t)id1 * D;
                float p0 = 0.f, p1 = 0.f;
                #pragma unroll
                for (int nt = 0; nt < 4; ++nt) {
                    int n0 = nq * 32 + nt * 8 + t2;
                    float b0 = bias_sm[n0], b1 = bias_sm[n0 + 1];
                    float v00 = acc[mt][nt][0] + b0, v01 = acc[mt][nt][1] + b1;
                    float v10 = acc[mt][nt][2] + b0, v11 = acc[mt][nt][3] + b1;
                    *(float2*)(o0 + n0) = make_float2(v00, v01);
                    *(float2*)(o1 + n0) = make_float2(v10, v11);
                    if (mode == 0) {
                        float w0 = sw_sm[n0], w1 = sw_sm[n0 + 1];
                        p0 += v00 * w0 + v01 * w1;
                        p1 += v10 * w0 + v11 * w1;
                    }
                }
                if (mode == 0) {
                    sc_sm[rr * 17 + slot4] = p0;
                    sc_sm[(rr + 8) * 17 + slot4] = p1;
                }
            }
        }
        __syncthreads();

        if (mode == 0) {
            // reduce 16 partials per row (fixed order -> deterministic)
            if (tid < 128) {
                int node = ids_sm[(it & 3) * 128 + tid];
                if (node >= LEAF0) {
                    const float* row = sc_sm + tid * 17;
                    float s = 0.f;
                    #pragma unroll
                    for (int k = 0; k < 16; ++k) s += row[k];
                    out[node] = s;
                }
            }
            __syncthreads();             // protect sc_sm before next epilogue
        }
    }
}

// emb[p] = (raw[p] + contrib[2p+1] + contrib[2p+2]) / 3 ; also out[p] = emb.w
__global__ void combine_kernel(int p0, int npar,
                               const float* __restrict__ score_W,
                               float* __restrict__ out) {
    int idx = blockIdx.x * blockDim.x + threadIdx.x;
    if (idx >= npar * 32) return;
    int i = idx >> 5, q = idx & 31;      // warp == one row
    int p = p0 + i;
    float4 r  = ((const float4*)(g_raw     + (size_t)p * D))[q];
    float4 c1 = ((const float4*)(g_contrib + (size_t)(2 * p + 1) * D))[q];
    float4 c2 = ((const float4*)(g_contrib + (size_t)(2 * p + 2) * D))[q];
    float4 h = make_float4((r.x + c1.x + c2.x) * (1.f / 3.f),
                           (r.y + c1.y + c2.y) * (1.f / 3.f),
                           (r.z + c1.z + c2.z) * (1.f / 3.f),
                           (r.w + c1.w + c2.w) * (1.f / 3.f));
    ((float4*)(g_emb + (size_t)p * D))[q] = h;
    float4 wv = __ldg(((const float4*)score_W) + q);
    float part = h.x * wv.x + h.y * wv.y + h.z * wv.z + h.w * wv.w;
    #pragma unroll
    for (int off = 16; off; off >>= 1)
        part += __shfl_xor_sync(0xffffffffu, part, off);
    if (q == 0) out[p] = part;
}

// ---------------------------------------------------------------------------
// Fused small levels (l = 9..0) with software grid barrier; scores fused.
// ---------------------------------------------------------------------------
#define NBL 128
__global__ void small_levels_kernel(const int* __restrict__ edges,
                                    const float* __restrict__ edge_W,
                                    const float* __restrict__ edge_b,
                                    const float* __restrict__ score_W,
                                    float* __restrict__ out)
{
    __shared__ float v1[D], v2[D], red[D], sw[D];
    const int tid = threadIdx.x;
    sw[tid] = score_W[tid];
    for (int l = 9; l >= 0; --l) {
        const int npar = 1 << l, p0 = npar - 1;
        for (int p = p0 + blockIdx.x; p < p0 + npar; p += NBL) {
            const int c1 = 2 * p + 1, c2 = 2 * p + 2;
            v1[tid] = fmaxf(g_emb[(size_t)c1 * D + tid], 0.f);
            v2[tid] = fmaxf(g_emb[(size_t)c2 * D + tid], 0.f);
            const int e1 = edges[c1], e2 = edges[c2];
            __syncthreads();
            const float* W1 = edge_W + (size_t)e1 * D * D + tid;
            const float* W2 = edge_W + (size_t)e2 * D * D + tid;
            float acc = edge_b[e1 * D + tid] + edge_b[e2 * D + tid];
            #pragma unroll 8
            for (int k = 0; k < D; ++k)
                acc += v1[k] * W1[k * D] + v2[k] * W2[k * D];
            float h = (g_raw[(size_t)p * D + tid] + acc) * (1.f / 3.f);
            g_emb[(size_t)p * D + tid] = h;
            red[tid] = h * sw[tid];
            __syncthreads();
            if (tid < 64) red[tid] += red[tid + 64];
            __syncthreads();
            if (tid < 32) {
                float s = red[tid] + red[tid + 32];
                #pragma unroll
                for (int off = 16; off; off >>= 1)
                    s += __shfl_xor_sync(0xffffffffu, s, off);
                if (tid == 0) out[p] = s;
            }
            __syncthreads();
        }
        grid_bar_n(NBL);
    }
}

extern "C" void kernel_launch(void* const* d_in, const int* in_sizes, int n_in,
                              void* d_out, int out_size)
{
    const int*   data      = (const int*)  d_in[0];
    const int*   edges     = (const int*)  d_in[1];
    const float* data_vecs = (const float*)d_in[2];
    const float* data_W    = (const float*)d_in[3];
    const float* data_b    = (const float*)d_in[4];
    const float* edge_W    = (const float*)d_in[5];
    const float* edge_b    = (const float*)d_in[6];
    const float* score_W   = (const float*)d_in[7];
    float* out = (float*)d_out;
    (void)in_sizes; (void)n_in; (void)out_size;

    cudaFuncSetAttribute(mma_gemm_kernel,
                         cudaFuncAttributeMaxDynamicSharedMemorySize, SM_TOT);

    int* d_count;
    cudaGetSymbolAddress((void**)&d_count, g_count);
    float* d_raw;
    cudaGetSymbolAddress((void**)&d_raw, g_raw);
    float* d_emb;
    cudaGetSymbolAddress((void**)&d_emb, g_emb);

    // prep_B also zeros bucket counters -> must precede bucket_kernel
    prep_B_kernel<<<9, 256>>>(data_W, edge_W);
    bucket_kernel<<<(NTOT - 2047 + 255) / 256, 256>>>(edges);

    // Embed (mode 0) — also emits leaf scores
    mma_gemm_kernel<<<148, 512, SM_TOT>>>(data, data_vecs, nullptr,
                                          nullptr, 0, 0,
                                          data_b, 0, 148, score_W, out);

    // Large levels: l = 16 .. 10  (GEMM over children, then combine+score)
    for (int l = 16; l >= 10; --l) {
        int dd = l + 1;
        int M2 = 1 << dd;                 // children count at this level
        int base = 8 * (M2 - 2);
        int npar = 1 << l;
        int p0 = npar - 1;
        int tiles_pe = (M2 / 8 + 127) >> 7;
        int nb = tiles_pe; if (nb < 1) nb = 1; if (nb > 18) nb = 18;
        const float* srcarr = (l == 16) ? d_raw : d_emb;
        mma_gemm_kernel<<<8 * nb, 512, SM_TOT>>>(nullptr, nullptr, srcarr,
                                                 d_count + l * 8, base, M2,
                                                 edge_b, (l == 16) ? 1 : 2, nb,
                                                 nullptr, nullptr);
        combine_kernel<<<(npar * 32 + 255) / 256, 256>>>(p0, npar, score_W, out);
    }

    // Small levels fused (l = 9..0) — scores fused
    small_levels_kernel<<<NBL, 128>>>(edges, edge_W, edge_b, score_W, out);
}

// round 17
// speedup vs baseline: 1.0516x; 1.0314x over previous
#include <cuda_runtime.h>
#include <cuda_bf16.h>
#include <cstdint>

#define D 128
#define NTOT ((1 << 18) - 1)      // 262143
#define LEAF0 ((1 << 17) - 1)     // 131071
#define LDK 136                    // bf16 pitch -> conflict-free ldmatrix

__device__ float g_raw[NTOT * D];          // embed output (= ret for leaves)
__device__ float g_emb[NTOT * D];          // emb for internal nodes
__device__ float g_contrib[NTOT * D];      // per-child contribution (incl. edge bias)
__device__ int   g_bucket[8 * (NTOT - 1)];
__device__ int   g_count[17 * 8];
__device__ __align__(16) __nv_bfloat16 g_Wt[9 * 2 * D * LDK];  // W^T hi/lo per matrix
__device__ int      g_bar_count;
__device__ unsigned g_bar_gen;

__device__ __forceinline__ uint32_t smem_to_u32(const void* p) {
    uint32_t a;
    asm("{ .reg .u64 t; cvta.to.shared.u64 t, %1; cvt.u32.u64 %0, t; }"
        : "=r"(a) : "l"(p));
    return a;
}
// split x into hi(bf16) + lo(bf16 residual); pack (x,y): low16=x, high16=y
__device__ __forceinline__ void split_pair(float x, float y, uint32_t& h, uint32_t& l) {
    asm("cvt.rn.bf16x2.f32 %0, %1, %2;" : "=r"(h) : "f"(y), "f"(x));
    float hx = __uint_as_float(h << 16);
    float hy = __uint_as_float(h & 0xffff0000u);
    asm("cvt.rn.bf16x2.f32 %0, %1, %2;" : "=r"(l) : "f"(y - hy), "f"(x - hx));
}
__device__ __forceinline__ void mma16816(float c[4], const uint32_t a[4],
                                         uint32_t b0, uint32_t b1) {
    asm volatile(
        "mma.sync.aligned.m16n8k16.row.col.f32.bf16.bf16.f32 "
        "{%0,%1,%2,%3}, {%4,%5,%6,%7}, {%8,%9}, {%0,%1,%2,%3};\n"
        : "+f"(c[0]), "+f"(c[1]), "+f"(c[2]), "+f"(c[3])
        : "r"(a[0]), "r"(a[1]), "r"(a[2]), "r"(a[3]), "r"(b0), "r"(b1));
}
__device__ __forceinline__ void ldsm4(uint32_t& r0, uint32_t& r1,
                                      uint32_t& r2, uint32_t& r3, uint32_t a) {
    asm volatile("ldmatrix.sync.aligned.m8n8.x4.shared.b16 {%0,%1,%2,%3}, [%4];"
                 : "=r"(r0), "=r"(r1), "=r"(r2), "=r"(r3) : "r"(a));
}

// ---- software grid barrier (co-resident blocks; self-resetting) ----
__device__ __forceinline__ void grid_bar_n(int nbl) {
    __syncthreads();
    if (threadIdx.x == 0) {
        unsigned gen = *((volatile unsigned*)&g_bar_gen);
        __threadfence();
        if (atomicAdd(&g_bar_count, 1) == nbl - 1) {
            g_bar_count = 0;
            __threadfence();
            atomicAdd(&g_bar_gen, 1u);
        } else {
            while (*((volatile unsigned*)&g_bar_gen) == gen) { }
        }
        __threadfence();
    }
    __syncthreads();
}

// ============================================================================
__global__ void bucket_kernel(const int* __restrict__ edges) {
    int c = blockIdx.x * blockDim.x + threadIdx.x + 2047;   // depth >= 11
    if (c >= NTOT) return;
    int d   = 31 - __clz(c + 1);
    int lev = d - 1;                    // parent level 10..16
    int M    = 1 << d;
    int base = 8 * (M - 2);
    int e = edges[c];
    int slot = atomicAdd(&g_count[lev * 8 + e], 1);
    g_bucket[base + e * M + slot] = c;
}

// W^T layout: Wt[n][k] pitch LDK, hi plane then lo plane. Block 0 also zeros
// the bucket counters (runs BEFORE bucket_kernel).
__global__ void prep_B_kernel(const float* __restrict__ data_W,
                              const float* __restrict__ edge_W) {
    int m = blockIdx.x;                 // 0..7 edges, 8 = data_W
    if (m == 0 && threadIdx.x < 17 * 8) g_count[threadIdx.x] = 0;
    const float* W = (m == 8) ? data_W : (edge_W + (size_t)m * D * D);
    __nv_bfloat16* dst = g_Wt + (size_t)m * 2 * D * LDK;
    for (int idx = threadIdx.x; idx < D * D; idx += blockDim.x) {
        int k = idx >> 7, n = idx & 127;
        float v = W[idx];
        __nv_bfloat16 h = __float2bfloat16(v);
        float hv = __bfloat162float(h);
        __nv_bfloat16 l = __float2bfloat16(v - hv);
        dst[n * LDK + k] = h;
        dst[D * LDK + n * LDK + k] = l;
    }
}

// ---------------------------------------------------------------------------
// R12 GEMM engine (UNCHANGED structure). Tile = 128x128, K = 128, split-bf16.
// mode 0 = embed over [0, count_in) node range (internal nodes only now),
// mode 1 = leaf children (g_raw), mode 2 = internal children (g_emb + relu).
// ---------------------------------------------------------------------------
#define SM_WH   0                       // 69632
#define SM_AH0  69632                   // 69632 (hi plane + lo plane @ +128*LDK)
#define SM_AH1  139264                  // 69632
#define SM_BIAS 208896                  // 512
#define SM_IDS  209408                  // 4 * 128 * 4 = 2048
#define SM_TOT  211456

__global__ void __launch_bounds__(512, 1)
mma_gemm_kernel(const int* __restrict__ data,
                const float* __restrict__ data_vecs,
                const float* __restrict__ srcarr,
                const int* __restrict__ counts, int bucket_base, int Mlist,
                const float* __restrict__ bias_all,
                int mode, int nb, int count_in)
{
    extern __shared__ unsigned char smem[];
    __nv_bfloat16* Wh = (__nv_bfloat16*)(smem + SM_WH);
    float* bias_sm = (float*)(smem + SM_BIAS);
    int*   ids_sm  = (int*)(smem + SM_IDS);

    const int tid = threadIdx.x;
    const int e  = (mode == 0) ? 8 : (blockIdx.x / nb);
    const int bi = (mode == 0) ? blockIdx.x : (blockIdx.x % nb);
    const int count = (mode == 0) ? count_in : counts[e];
    if (count == 0) return;
    const int ntiles = (count + 127) >> 7;
    if (bi >= ntiles) return;
    const int niter = (ntiles - bi + nb - 1) / nb;
    const int relu = (mode == 2);

    const uint32_t smem_u = smem_to_u32(smem);
    const int* list = g_bucket + bucket_base + (size_t)e * Mlist;
    float* outbase = (mode == 0) ? g_raw : g_contrib;

    const int fr = tid >> 2;            // fetch row 0..127
    const int fq = tid & 3;             // row quarter (8 float4)

    float4 vreg[8];

    auto ldg_tile = [&](int it) {
        int tile = bi + it * nb;
        int jj = min(tile * 128 + fr, count - 1);
        int id = (mode == 0) ? jj : list[jj];
        if (fq == 0) ids_sm[(it & 3) * 128 + fr] = id;
        const float4* src = (mode == 0)
            ? (const float4*)(data_vecs + (size_t)__ldg(&data[jj]) * D)
            : (const float4*)(srcarr + (size_t)id * D);
        #pragma unroll
        for (int i = 0; i < 8; ++i)
            vreg[i] = src[fq * 8 + i];
    };

    auto convert = [&](int it) {
        __nv_bfloat16* Ah = (__nv_bfloat16*)(smem + ((it & 1) ? SM_AH1 : SM_AH0));
        #pragma unroll
        for (int i = 0; i < 8; ++i) {
            float4 v = vreg[i];
            if (relu) {
                v.x = fmaxf(v.x, 0.f); v.y = fmaxf(v.y, 0.f);
                v.z = fmaxf(v.z, 0.f); v.w = fmaxf(v.w, 0.f);
            }
            uint32_t h0, l0, h1, l1;
            split_pair(v.x, v.y, h0, l0);
            split_pair(v.z, v.w, h1, l1);
            int c = fq * 32 + i * 4;
            *(uint2*)(Ah + fr * LDK + c)             = make_uint2(h0, h1);
            *(uint2*)(Ah + 128 * LDK + fr * LDK + c) = make_uint2(l0, l1);
        }
    };

    // ---- prologue ----
    ldg_tile(0);
    {
        const uint4* src = (const uint4*)(g_Wt + (size_t)e * 2 * D * LDK);
        uint4* dst = (uint4*)Wh;
        for (int i = tid; i < 4352; i += 512) dst[i] = src[i];
        const float* bias = (mode == 0) ? bias_all : (bias_all + e * D);
        if (tid < D) bias_sm[tid] = bias[tid];
    }
    convert(0);
    if (niter > 1) ldg_tile(1);
    __syncthreads();

    // ---- warp tiling ----
    const int lane = tid & 31;
    const int warp = tid >> 5;
    const int mq = warp & 3;
    const int nq = warp >> 2;
    const int g  = lane >> 2;
    const int t2 = (lane & 3) * 2;

    uint32_t aAddr[2][2][2], wAddr[2][2];
    #pragma unroll
    for (int b = 0; b < 2; ++b)
        #pragma unroll
        for (int mt = 0; mt < 2; ++mt)
            #pragma unroll
            for (int pl = 0; pl < 2; ++pl)
                aAddr[b][mt][pl] = smem_u + (b ? SM_AH1 : SM_AH0) +
                    ((pl * 128 + mq * 32 + mt * 16 + (lane & 15)) * LDK
                     + (lane >> 4) * 8) * 2;
    #pragma unroll
    for (int q = 0; q < 2; ++q)
        #pragma unroll
        for (int pl = 0; pl < 2; ++pl)
            wAddr[q][pl] = smem_u + SM_WH +
                ((pl * 128 + nq * 32 + q * 16 + ((lane >> 4) & 1) * 8 + (lane & 7)) * LDK
                 + ((lane >> 3) & 1) * 8) * 2;

    for (int it = 0; it < niter; ++it) {
        const int pb = it & 1;

        float acc[2][4][4];
        #pragma unroll
        for (int mt = 0; mt < 2; ++mt)
            #pragma unroll
            for (int nt = 0; nt < 4; ++nt)
                #pragma unroll
                for (int i = 0; i < 4; ++i) acc[mt][nt][i] = 0.f;

        #pragma unroll
        for (int ks = 0; ks < 8; ++ks) {
            const uint32_t kb = ks * 32;
            uint32_t ah[2][4], al[2][4];
            #pragma unroll
            for (int mt = 0; mt < 2; ++mt) {
                ldsm4(ah[mt][0], ah[mt][1], ah[mt][2], ah[mt][3],
                      aAddr[pb][mt][0] + kb);
                ldsm4(al[mt][0], al[mt][1], al[mt][2], al[mt][3],
                      aAddr[pb][mt][1] + kb);
            }
            uint32_t bh[4][2], bl[4][2];
            #pragma unroll
            for (int q = 0; q < 2; ++q) {
                ldsm4(bh[2 * q][0], bh[2 * q][1], bh[2 * q + 1][0], bh[2 * q + 1][1],
                      wAddr[q][0] + kb);
                ldsm4(bl[2 * q][0], bl[2 * q][1], bl[2 * q + 1][0], bl[2 * q + 1][1],
                      wAddr[q][1] + kb);
            }
            #pragma unroll
            for (int mt = 0; mt < 2; ++mt)
                #pragma unroll
                for (int nt = 0; nt < 4; ++nt) {
                    mma16816(acc[mt][nt], ah[mt], bh[nt][0], bh[nt][1]);   // hi*Whi
                    mma16816(acc[mt][nt], al[mt], bh[nt][0], bh[nt][1]);   // lo*Whi
                    mma16816(acc[mt][nt], ah[mt], bl[nt][0], bl[nt][1]);   // hi*Wlo
                }
        }

        if (it + 1 < niter) convert(it + 1);
        if (it + 2 < niter) ldg_tile(it + 2);

        {
            const int slot = (it & 3) * 128;
            #pragma unroll
            for (int mt = 0; mt < 2; ++mt) {
                int rr = mq * 32 + mt * 16 + g;
                int id0 = ids_sm[slot + rr];
                int id1 = ids_sm[slot + rr + 8];
                float* o0 = outbase + (size_t)id0 * D;
                float* o1 = outbase + (size_t)id1 * D;
                #pragma unroll
                for (int nt = 0; nt < 4; ++nt) {
                    int n0 = nq * 32 + nt * 8 + t2;
                    float b0 = bias_sm[n0], b1 = bias_sm[n0 + 1];
                    *(float2*)(o0 + n0) = make_float2(acc[mt][nt][0] + b0,
                                                      acc[mt][nt][1] + b1);
                    *(float2*)(o1 + n0) = make_float2(acc[mt][nt][2] + b0,
                                                      acc[mt][nt][3] + b1);
                }
            }
        }
        __syncthreads();
    }
}

// ---------------------------------------------------------------------------
// Fused leaf kernel: per 128-leaf tile (bucketed by edge e):
//   gather data_vecs -> MMA x data_W -> raw (STG g_raw, kept in acc)
//   -> split(acc) -> Ah -> MMA x edge_W[e] -> contrib (STG g_contrib)
// Intermediate never touches DRAM; staging amortized over 2 GEMMs.
// ---------------------------------------------------------------------------
#define FL_WD   0                       // 69632 (data_W hi/lo)
#define FL_WE   69632                   // 69632 (edge_W[e] hi/lo)
#define FL_AH   139264                  // 69632 (single A buffer)
#define FL_BD   208896                  // 512
#define FL_BE   209408                  // 512
#define FL_IDS  209920                  // 4*128*4 = 2048
#define FL_TOT  211968

__global__ void __launch_bounds__(512, 1)
fused_leaf_kernel(const int* __restrict__ data,
                  const float* __restrict__ data_vecs,
                  const int* __restrict__ counts, int bucket_base, int Mlist,
                  const float* __restrict__ data_b,
                  const float* __restrict__ edge_b,
                  int nb)
{
    extern __shared__ unsigned char smem[];
    float* bd_sm = (float*)(smem + FL_BD);
    float* be_sm = (float*)(smem + FL_BE);
    int*   ids_sm = (int*)(smem + FL_IDS);

    const int tid = threadIdx.x;
    const int e  = blockIdx.x / nb;
    const int bi = blockIdx.x % nb;
    const int count = counts[e];
    if (count == 0) return;
    const int ntiles = (count + 127) >> 7;
    if (bi >= ntiles) return;
    const int niter = (ntiles - bi + nb - 1) / nb;

    const uint32_t smem_u = smem_to_u32(smem);
    const int* list = g_bucket + bucket_base + (size_t)e * Mlist;

    const int fr = tid >> 2;
    const int fq = tid & 3;

    float4 vreg[8];

    auto ldg_tile = [&](int it) {
        int tile = bi + it * nb;
        int jj = min(tile * 128 + fr, count - 1);
        int id = list[jj];
        if (fq == 0) ids_sm[(it & 3) * 128 + fr] = id;
        const float4* src = (const float4*)(data_vecs + (size_t)__ldg(&data[id]) * D);
        #pragma unroll
        for (int i = 0; i < 8; ++i)
            vreg[i] = src[fq * 8 + i];
    };

    auto convert1 = [&]() {             // vreg -> Ah (no relu)
        __nv_bfloat16* Ah = (__nv_bfloat16*)(smem + FL_AH);
        #pragma unroll
        for (int i = 0; i < 8; ++i) {
            float4 v = vreg[i];
            uint32_t h0, l0, h1, l1;
            split_pair(v.x, v.y, h0, l0);
            split_pair(v.z, v.w, h1, l1);
            int c = fq * 32 + i * 4;
            *(uint2*)(Ah + fr * LDK + c)             = make_uint2(h0, h1);
            *(uint2*)(Ah + 128 * LDK + fr * LDK + c) = make_uint2(l0, l1);
        }
    };

    // ---- prologue: fetch tile 0, stage both W banks + biases ----
    ldg_tile(0);
    {
        const uint4* srcD = (const uint4*)(g_Wt + (size_t)8 * 2 * D * LDK);
        const uint4* srcE = (const uint4*)(g_Wt + (size_t)e * 2 * D * LDK);
        uint4* dstD = (uint4*)(smem + FL_WD);
        uint4* dstE = (uint4*)(smem + FL_WE);
        for (int i = tid; i < 4352; i += 512) { dstD[i] = srcD[i]; dstE[i] = srcE[i]; }
        if (tid < D) bd_sm[tid] = data_b[tid];
        else if (tid >= 128 && tid < 256) be_sm[tid - 128] = edge_b[e * D + tid - 128];
    }
    convert1();
    if (niter > 1) ldg_tile(1);
    __syncthreads();

    // ---- warp tiling ----
    const int lane = tid & 31;
    const int warp = tid >> 5;
    const int mq = warp & 3;
    const int nq = warp >> 2;
    const int g  = lane >> 2;
    const int t2 = (lane & 3) * 2;

    uint32_t aAddr[2][2], wAddr[2][2];
    #pragma unroll
    for (int mt = 0; mt < 2; ++mt)
        #pragma unroll
        for (int pl = 0; pl < 2; ++pl)
            aAddr[mt][pl] = smem_u + FL_AH +
                ((pl * 128 + mq * 32 + mt * 16 + (lane & 15)) * LDK
                 + (lane >> 4) * 8) * 2;
    #pragma unroll
    for (int q = 0; q < 2; ++q)
        #pragma unroll
        for (int pl = 0; pl < 2; ++pl)
            wAddr[q][pl] = smem_u + FL_WD +
                ((pl * 128 + nq * 32 + q * 16 + ((lane >> 4) & 1) * 8 + (lane & 7)) * LDK
                 + ((lane >> 3) & 1) * 8) * 2;
    const uint32_t WE_OFF = FL_WE - FL_WD;

    __nv_bfloat16* Ah = (__nv_bfloat16*)(smem + FL_AH);

    for (int it = 0; it < niter; ++it) {
        const int slot = (it & 3) * 128;

        // ================= GEMM 1: A x data_W =================
        float acc[2][4][4];
        #pragma unroll
        for (int mt = 0; mt < 2; ++mt)
            #pragma unroll
            for (int nt = 0; nt < 4; ++nt)
                #pragma unroll
                for (int i = 0; i < 4; ++i) acc[mt][nt][i] = 0.f;

        #pragma unroll
        for (int ks = 0; ks < 8; ++ks) {
            const uint32_t kb = ks * 32;
            uint32_t ah[2][4], al[2][4];
            #pragma unroll
            for (int mt = 0; mt < 2; ++mt) {
                ldsm4(ah[mt][0], ah[mt][1], ah[mt][2], ah[mt][3], aAddr[mt][0] + kb);
                ldsm4(al[mt][0], al[mt][1], al[mt][2], al[mt][3], aAddr[mt][1] + kb);
            }
            uint32_t bh[4][2], bl[4][2];
            #pragma unroll
            for (int q = 0; q < 2; ++q) {
                ldsm4(bh[2 * q][0], bh[2 * q][1], bh[2 * q + 1][0], bh[2 * q + 1][1],
                      wAddr[q][0] + kb);
                ldsm4(bl[2 * q][0], bl[2 * q][1], bl[2 * q + 1][0], bl[2 * q + 1][1],
                      wAddr[q][1] + kb);
            }
            #pragma unroll
            for (int mt = 0; mt < 2; ++mt)
                #pragma unroll
                for (int nt = 0; nt < 4; ++nt) {
                    mma16816(acc[mt][nt], ah[mt], bh[nt][0], bh[nt][1]);
                    mma16816(acc[mt][nt], al[mt], bh[nt][0], bh[nt][1]);
                    mma16816(acc[mt][nt], ah[mt], bl[nt][0], bl[nt][1]);
                }
        }
        __syncthreads();                 // all MMA1 reads of Ah done

        // ---- epi1: raw = acc + data_b -> STG g_raw ; split -> Ah ----
        #pragma unroll
        for (int mt = 0; mt < 2; ++mt) {
            int rr = mq * 32 + mt * 16 + g;
            int id0 = ids_sm[slot + rr];
            int id1 = ids_sm[slot + rr + 8];
            float* o0 = g_raw + (size_t)id0 * D;
            float* o1 = g_raw + (size_t)id1 * D;
            #pragma unroll
            for (int nt = 0; nt < 4; ++nt) {
                int n0 = nq * 32 + nt * 8 + t2;
                float b0 = bd_sm[n0], b1 = bd_sm[n0 + 1];
                float v00 = acc[mt][nt][0] + b0, v01 = acc[mt][nt][1] + b1;
                float v10 = acc[mt][nt][2] + b0, v11 = acc[mt][nt][3] + b1;
                *(float2*)(o0 + n0) = make_float2(v00, v01);
                *(float2*)(o1 + n0) = make_float2(v10, v11);
                uint32_t h, l;
                split_pair(v00, v01, h, l);
                *(uint32_t*)(Ah + rr * LDK + n0) = h;
                *(uint32_t*)(Ah + 128 * LDK + rr * LDK + n0) = l;
                split_pair(v10, v11, h, l);
                *(uint32_t*)(Ah + (rr + 8) * LDK + n0) = h;
                *(uint32_t*)(Ah + 128 * LDK + (rr + 8) * LDK + n0) = l;
            }
        }
        __syncthreads();                 // Ah now holds raw tile

        // ================= GEMM 2: raw x edge_W[e] =================
        #pragma unroll
        for (int mt = 0; mt < 2; ++mt)
            #pragma unroll
            for (int nt = 0; nt < 4; ++nt)
                #pragma unroll
                for (int i = 0; i < 4; ++i) acc[mt][nt][i] = 0.f;

        #pragma unroll
        for (int ks = 0; ks < 8; ++ks) {
            const uint32_t kb = ks * 32;
            uint32_t ah[2][4], al[2][4];
            #pragma unroll
            for (int mt = 0; mt < 2; ++mt) {
                ldsm4(ah[mt][0], ah[mt][1], ah[mt][2], ah[mt][3], aAddr[mt][0] + kb);
                ldsm4(al[mt][0], al[mt][1], al[mt][2], al[mt][3], aAddr[mt][1] + kb);
            }
            uint32_t bh[4][2], bl[4][2];
            #pragma unroll
            for (int q = 0; q < 2; ++q) {
                ldsm4(bh[2 * q][0], bh[2 * q][1], bh[2 * q + 1][0], bh[2 * q + 1][1],
                      wAddr[q][0] + WE_OFF + kb);
                ldsm4(bl[2 * q][0], bl[2 * q][1], bl[2 * q + 1][0], bl[2 * q + 1][1],
                      wAddr[q][1] + WE_OFF + kb);
            }
            #pragma unroll
            for (int mt = 0; mt < 2; ++mt)
                #pragma unroll
                for (int nt = 0; nt < 4; ++nt) {
                    mma16816(acc[mt][nt], ah[mt], bh[nt][0], bh[nt][1]);
                    mma16816(acc[mt][nt], al[mt], bh[nt][0], bh[nt][1]);
                    mma16816(acc[mt][nt], ah[mt], bl[nt][0], bl[nt][1]);
                }
        }

        // ---- epi2: contrib = acc + edge_b[e] -> STG g_contrib ----
        #pragma unroll
        for (int mt = 0; mt < 2; ++mt) {
            int rr = mq * 32 + mt * 16 + g;
            int id0 = ids_sm[slot + rr];
            int id1 = ids_sm[slot + rr + 8];
            float* o0 = g_contrib + (size_t)id0 * D;
            float* o1 = g_contrib + (size_t)id1 * D;
            #pragma unroll
            for (int nt = 0; nt < 4; ++nt) {
                int n0 = nq * 32 + nt * 8 + t2;
                float b0 = be_sm[n0], b1 = be_sm[n0 + 1];
                *(float2*)(o0 + n0) = make_float2(acc[mt][nt][0] + b0,
                                                  acc[mt][nt][1] + b1);
                *(float2*)(o1 + n0) = make_float2(acc[mt][nt][2] + b0,
                                                  acc[mt][nt][3] + b1);
            }
        }
        __syncthreads();                 // all MMA2 reads done

        if (it + 1 < niter) {
            convert1();                  // vreg(it+1) -> Ah
            if (it + 2 < niter) ldg_tile(it + 2);
        }
        __syncthreads();                 // Ah ready for next iter
    }
}

// emb[p] = (raw[p] + contrib[2p+1] + contrib[2p+2]) / 3
__global__ void combine_kernel(int p0, int npar) {
    int idx = blockIdx.x * blockDim.x + threadIdx.x;
    if (idx >= npar * 32) return;
    int i = idx >> 5, q = idx & 31;
    int p = p0 + i;
    float4 r  = ((const float4*)(g_raw     + (size_t)p * D))[q];
    float4 c1 = ((const float4*)(g_contrib + (size_t)(2 * p + 1) * D))[q];
    float4 c2 = ((const float4*)(g_contrib + (size_t)(2 * p + 2) * D))[q];
    float4 h = make_float4((r.x + c1.x + c2.x) * (1.f / 3.f),
                           (r.y + c1.y + c2.y) * (1.f / 3.f),
                           (r.z + c1.z + c2.z) * (1.f / 3.f),
                           (r.w + c1.w + c2.w) * (1.f / 3.f));
    ((float4*)(g_emb + (size_t)p * D))[q] = h;
}

// ---------------------------------------------------------------------------
// Fused small levels (l = 9..0) with software grid barrier.
// ---------------------------------------------------------------------------
#define NBL 128
__global__ void small_levels_kernel(const int* __restrict__ edges,
                                    const float* __restrict__ edge_W,
                                    const float* __restrict__ edge_b)
{
    __shared__ float v1[D], v2[D];
    const int tid = threadIdx.x;
    for (int l = 9; l >= 0; --l) {
        const int npar = 1 << l, p0 = npar - 1;
        for (int p = p0 + blockIdx.x; p < p0 + npar; p += NBL) {
            const int c1 = 2 * p + 1, c2 = 2 * p + 2;
            v1[tid] = fmaxf(g_emb[(size_t)c1 * D + tid], 0.f);
            v2[tid] = fmaxf(g_emb[(size_t)c2 * D + tid], 0.f);
            const int e1 = edges[c1], e2 = edges[c2];
            __syncthreads();
            const float* W1 = edge_W + (size_t)e1 * D * D + tid;
            const float* W2 = edge_W + (size_t)e2 * D * D + tid;
            float acc = edge_b[e1 * D + tid] + edge_b[e2 * D + tid];
            #pragma unroll 8
            for (int k = 0; k < D; ++k)
                acc += v1[k] * W1[k * D] + v2[k] * W2[k * D];
            float h = (g_raw[(size_t)p * D + tid] + acc) * (1.f / 3.f);
            g_emb[(size_t)p * D + tid] = h;
            __syncthreads();
        }
        grid_bar_n(NBL);
    }
}

// ---------------------------------------------------------------------------
// Scores: internal -> g_emb, leaves -> g_raw
// ---------------------------------------------------------------------------
__global__ void score_kernel(const float* __restrict__ score_W,
                             float* __restrict__ out)
{
    __shared__ float sW[D];
    const int tid = threadIdx.x;
    if (tid < D) sW[tid] = score_W[tid];
    __syncthreads();
    const int w = tid >> 5, lane = tid & 31;
    const float4 s4 = ((const float4*)sW)[lane];
    const int gw = blockIdx.x * 8 + w;
    const int nw = gridDim.x * 8;
    for (int node = gw; node < NTOT; node += nw) {
        const float* src = (node < LEAF0) ? g_emb : g_raw;
        float4 v = ((const float4*)(src + (size_t)node * D))[lane];
        float d = v.x * s4.x + v.y * s4.y + v.z * s4.z + v.w * s4.w;
        #pragma unroll
        for (int off = 16; off; off >>= 1)
            d += __shfl_xor_sync(0xffffffffu, d, off);
        if (lane == 0) out[node] = d;
    }
}

extern "C" void kernel_launch(void* const* d_in, const int* in_sizes, int n_in,
                              void* d_out, int out_size)
{
    const int*   data      = (const int*)  d_in[0];
    const int*   edges     = (const int*)  d_in[1];
    const float* data_vecs = (const float*)d_in[2];
    const float* data_W    = (const float*)d_in[3];
    const float* data_b    = (const float*)d_in[4];
    const float* edge_W    = (const float*)d_in[5];
    const float* edge_b    = (const float*)d_in[6];
    const float* score_W   = (const float*)d_in[7];
    float* out = (float*)d_out;
    (void)in_sizes; (void)n_in; (void)out_size;

    cudaFuncSetAttribute(mma_gemm_kernel,
                         cudaFuncAttributeMaxDynamicSharedMemorySize, SM_TOT);
    cudaFuncSetAttribute(fused_leaf_kernel,
                         cudaFuncAttributeMaxDynamicSharedMemorySize, FL_TOT);

    int* d_count;
    cudaGetSymbolAddress((void**)&d_count, g_count);
    float* d_emb;
    cudaGetSymbolAddress((void**)&d_emb, g_emb);

    // prep_B also zeros bucket counters -> must precede bucket_kernel
    prep_B_kernel<<<9, 256>>>(data_W, edge_W);
    bucket_kernel<<<(NTOT - 2047 + 255) / 256, 256>>>(edges);

    // Embed internal nodes only (mode 0, count = LEAF0)
    mma_gemm_kernel<<<148, 512, SM_TOT>>>(data, data_vecs, nullptr,
                                          nullptr, 0, 0,
                                          data_b, 0, 148, LEAF0);

    // Fused leaf: embed leaves + level-16 edge GEMM in one pass
    {
        int M2 = 1 << 17;                 // children count at level 16
        int base = 8 * (M2 - 2);
        int nb = 18;
        fused_leaf_kernel<<<8 * nb, 512, FL_TOT>>>(data, data_vecs,
                                                   d_count + 16 * 8, base, M2,
                                                   data_b, edge_b, nb);
        int npar = 1 << 16;
        combine_kernel<<<(npar * 32 + 255) / 256, 256>>>(npar - 1, npar);
    }

    // Levels l = 15 .. 10  (GEMM over children, then combine)
    for (int l = 15; l >= 10; --l) {
        int dd = l + 1;
        int M2 = 1 << dd;
        int base = 8 * (M2 - 2);
        int npar = 1 << l;
        int p0 = npar - 1;
        int tiles_pe = (M2 / 8 + 127) >> 7;
        int nb = tiles_pe; if (nb < 1) nb = 1; if (nb > 18) nb = 18;
        mma_gemm_kernel<<<8 * nb, 512, SM_TOT>>>(nullptr, nullptr, d_emb,
                                                 d_count + l * 8, base, M2,
                                                 edge_b, 2, nb, 0);
        combine_kernel<<<(npar * 32 + 255) / 256, 256>>>(p0, npar);
    }

    // Small levels fused (l = 9..0)
    small_levels_kernel<<<NBL, 128>>>(edges, edge_W, edge_b);

    score_kernel<<<592, 256>>>(score_W, out);
}